// round 12
// baseline (speedup 1.0000x reference)
#include <cuda_runtime.h>
#include <math.h>

#define T_ 64
#define B_ 64
#define N_ 64
#define H_ 2
#define KK_ 16
#define PLANE (64*64*128)

typedef unsigned long long u64;
typedef unsigned int u32;

__device__ float g_Cl[KK_*T_];
__device__ u64 g_qbits[(size_t)T_*B_*H_*N_];
__device__ u64 g_kbits[(size_t)T_*B_*H_*N_];
__device__ u64 g_vbits[(size_t)T_*B_*H_*N_];
__device__ u64 g_abits[(size_t)T_*B_*N_*H_];
__device__ u64 g_m1bits[(size_t)T_*B_*N_*4];
__device__ float g_o[(size_t)T_*B_*N_*128];

namespace {
struct ModuleWarm { ModuleWarm() { void* p = nullptr; (void)cudaGetSymbolAddress(&p, g_qbits); } };
static ModuleWarm s_mw;
}

__device__ __forceinline__ void ffma2(u64 &d, u64 a, u64 b) {
    asm("fma.rn.f32x2 %0, %1, %2, %0;" : "+l"(d) : "l"(a), "l"(b));
}
__device__ __forceinline__ u64 pk2(float lo, float hi) {
    u64 r; asm("mov.b64 %0, {%1,%2};" : "=l"(r) : "f"(lo), "f"(hi)); return r;
}
__device__ __forceinline__ float2 up2(u64 v) {
    float2 f; asm("mov.b64 {%0,%1}, %2;" : "=f"(f.x), "=f"(f.y) : "l"(v)); return f;
}

__global__ void k_nop() {}

__global__ void k_dct() {
    int t = threadIdx.x, k = threadIdx.y;
    double c = cos(M_PI * ((double)t + 0.5) * (double)k / 64.0) * sqrt(2.0 / 64.0);
    if (k == 0) c *= (1.0 / sqrt(2.0));
    g_Cl[k*T_ + t] = (float)c;
}

// smem map (floats): [0,16384) As2 | [16384,32768) Ws2 ; Cs aliases [0,16384);
// Xs aliases [16384,..) ; extras at 32768+.
#define SBASE 32768

// W interleave: Ws2[kp][col] = (W[2kp][coff+col], W[2kp+1][coff+col])
__device__ __forceinline__ void build_W(u64* Ws2, const float* __restrict__ W,
                                        int wstride, int coff, int tid) {
    int kp = tid >> 5, cq = tid & 31;
    #pragma unroll
    for (int j = 0; j < 2; j++) {
        int kpp = kp + 32*j;
        const float* w0 = W + (size_t)(2*kpp)*wstride + coff + cq*4;
        float4 r0 = *(const float4*)w0;
        float4 r1 = *(const float4*)(w0 + wstride);
        ulonglong2* wd = (ulonglong2*)(Ws2 + kpp*128 + cq*4);
        wd[0] = make_ulonglong2(pk2(r0.x, r1.x), pk2(r0.y, r1.y));
        wd[1] = make_ulonglong2(pk2(r0.z, r1.z), pk2(r0.w, r1.w));
    }
}

// 128 rows x 128 cols, 64 k-pairs. 32 warps: rowg=w>>1 (8 rows), c0=(w&1)*64+lane*2.
__device__ __forceinline__ void gemm_core(const u64* As2, const u64* Ws2,
                                          u64 (&acc)[8][2], int rowg, int c0) {
    #pragma unroll 4
    for (int kp = 0; kp < 64; kp++) {
        const u64* ar = As2 + kp*128 + rowg*8;
        ulonglong2 w01 = *(const ulonglong2*)(Ws2 + kp*128 + c0);
        ulonglong2 a01 = *(const ulonglong2*)ar;
        ulonglong2 a23 = *(const ulonglong2*)(ar + 2);
        ffma2(acc[0][0], a01.x, w01.x); ffma2(acc[0][1], a01.x, w01.y);
        ffma2(acc[1][0], a01.y, w01.x); ffma2(acc[1][1], a01.y, w01.y);
        ffma2(acc[2][0], a23.x, w01.x); ffma2(acc[2][1], a23.x, w01.y);
        ffma2(acc[3][0], a23.y, w01.x); ffma2(acc[3][1], a23.y, w01.y);
        ulonglong2 a45 = *(const ulonglong2*)(ar + 4);
        ulonglong2 a67 = *(const ulonglong2*)(ar + 6);
        ffma2(acc[4][0], a45.x, w01.x); ffma2(acc[4][1], a45.x, w01.y);
        ffma2(acc[5][0], a45.y, w01.x); ffma2(acc[5][1], a45.y, w01.y);
        ffma2(acc[6][0], a67.x, w01.x); ffma2(acc[6][1], a67.x, w01.y);
        ffma2(acc[7][0], a67.y, w01.x); ffma2(acc[7][1], a67.y, w01.y);
    }
}

__device__ __forceinline__ void store_c(float* Cs, u64 (&acc)[8][2], int rowg, int c0) {
    #pragma unroll
    for (int i = 0; i < 8; i++) {
        float2 f0 = up2(acc[i][0]), f1 = up2(acc[i][1]);
        *(float2*)(Cs + (rowg*8 + i)*128 + c0) = make_float2(f0.x + f0.y, f1.x + f1.y);
    }
}

#define ZACC u64 acc[8][2]; _Pragma("unroll") for (int i_ = 0; i_ < 8; i_++) { acc[i_][0] = 0ull; acc[i_][1] = 0ull; }

// ---------------- K1/K5: src @ W(128x128) + LIF -> q bits / attn-gate bits ----
#define SMEM_G (131072 + 2048)
__global__ __launch_bounds__(1024, 1) void k_g128(const float* __restrict__ src,
                                                  const float* __restrict__ W,
                                                  int mode) {
    extern __shared__ float sm[];
    u64* As2 = (u64*)sm;
    u64* Ws2 = As2 + 8192;
    float* Cs = sm;
    u32* sbal = (u32*)(sm + SBASE);
    int tid = threadIdx.x, bn0 = blockIdx.x*2;

    {   // A pack
        int row = tid >> 3, kq0 = tid & 7;
        int bnl = row >> 6, t = row & 63;
        const float4* sp = (const float4*)(src + (size_t)(bn0 + bnl)*128 + (size_t)t*PLANE);
        #pragma unroll
        for (int i = 0; i < 4; i++) {
            int kqq = kq0 + 8*i;
            float4 v = sp[kqq];
            As2[(2*kqq)*128 + row]   = pk2(v.x, v.y);
            As2[(2*kqq+1)*128 + row] = pk2(v.z, v.w);
        }
    }
    build_W(Ws2, W, 128, 0, tid);
    __syncthreads();

    ZACC;
    int w = tid >> 5, lane = tid & 31;
    int rowg = w >> 1, c0 = (w & 1)*64 + lane*2;
    gemm_core(As2, Ws2, acc, rowg, c0);
    __syncthreads();
    store_c(Cs, acc, rowg, c0);
    __syncthreads();

    if (tid < 256) {
        int bnl = tid >> 7, col = tid & 127;
        float v = 0.f;
        for (int t = 0; t < T_; t++) {
            float c = Cs[(bnl*64 + t)*128 + col];
            v += (c - v)*0.5f;
            bool s = (v >= 1.0f); if (s) v = 0.f;
            u32 bal = __ballot_sync(0xffffffffu, s);
            if ((tid & 31) == 0) sbal[t*8 + (tid >> 5)] = bal;
        }
    }
    __syncthreads();
    if (tid < 256) {
        int bnl = tid >> 7, rr = tid & 127, t = rr >> 1, h = rr & 1;
        int g = bnl*4 + 2*h;
        u64 bits = (u64)sbal[t*8 + g] | ((u64)sbal[t*8 + g + 1] << 32);
        int bn = bn0 + bnl, b = bn >> 6, n = bn & 63;
        if (mode == 0) g_qbits[(((size_t)t*B_ + b)*H_ + h)*N_ + n] = bits;
        else           g_abits[(((size_t)t*B_ + b)*N_ + n)*H_ + h] = bits;
    }
}

// ---------------- K2: (x*mx) @ (Wk|Wv by gy) + lowpass + LIF ------------------
#define SMEM_KV (131072 + 4096 + 2048)
__global__ __launch_bounds__(1024, 1) void k_kv(const float* __restrict__ x,
                                                const float* __restrict__ mx,
                                                const float* __restrict__ Wk,
                                                const float* __restrict__ Wv) {
    extern __shared__ float sm[];
    u64* As2 = (u64*)sm;
    u64* Ws2 = As2 + 8192;
    float* Cs = sm;
    float* Xs = sm + 16384;          // aliases Ws2 (dead post-GEMM): 2*128*16
    float* sCl = sm + SBASE;
    u32* sbal = (u32*)(sm + SBASE + 1024);
    int tid = threadIdx.x, bn0 = blockIdx.x*2, gy = blockIdx.y;

    {   // A pack: raw x*mx (lowpass commutes with the feature GEMM)
        int row = tid >> 3, kq0 = tid & 7;
        int bnl = row >> 6, t = row & 63;
        int bn = bn0 + bnl, b = bn >> 6, n = bn & 63;
        const float4* xp = (const float4*)(x + (size_t)bn*128 + (size_t)t*PLANE);
        const float4* mp = (const float4*)(mx + ((size_t)n*B_ + b)*T_*128 + (size_t)t*128);
        #pragma unroll
        for (int i = 0; i < 4; i++) {
            int kqq = kq0 + 8*i;
            float4 v = xp[kqq], m = mp[kqq];
            m.x = 0.05f*m.x + 0.95f*m.x; m.y = 0.05f*m.y + 0.95f*m.y;
            m.z = 0.05f*m.z + 0.95f*m.z; m.w = 0.05f*m.w + 0.95f*m.w;
            As2[(2*kqq)*128 + row]   = pk2(v.x*m.x, v.y*m.y);
            As2[(2*kqq+1)*128 + row] = pk2(v.z*m.z, v.w*m.w);
        }
    }
    build_W(Ws2, gy ? Wv : Wk, 128, 0, tid);
    if (tid < 1024) sCl[tid] = g_Cl[tid];
    __syncthreads();

    ZACC;
    int w = tid >> 5, lane = tid & 31;
    int rowg = w >> 1, c0 = (w & 1)*64 + lane*2;
    gemm_core(As2, Ws2, acc, rowg, c0);
    __syncthreads();
    store_c(Cs, acc, rowg, c0);
    __syncthreads();

    {   // lowpass stage 1: Xk = Cl @ C_t, parallel over (bnl,col,kq)
        int bnl = tid >> 9, rem = tid & 511, col = rem >> 2, kq = rem & 3;
        float s0 = 0.f, s1 = 0.f, s2 = 0.f, s3 = 0.f;
        const float* cb = Cs + bnl*64*128 + col;
        const float* cl = sCl + kq*4*64;
        for (int t = 0; t < T_; t++) {
            float c = cb[t*128];
            s0 += cl[t]*c; s1 += cl[64 + t]*c; s2 += cl[128 + t]*c; s3 += cl[192 + t]*c;
        }
        float* xd = Xs + bnl*2048 + col*16 + kq*4;
        xd[0] = s0; xd[1] = s1; xd[2] = s2; xd[3] = s3;
    }
    __syncthreads();

    if (tid < 256) {   // stage 2: reconstruct + LIF
        int bnl = tid >> 7, col = tid & 127;
        float xk[KK_];
        #pragma unroll
        for (int k = 0; k < KK_; k++) xk[k] = Xs[bnl*2048 + col*16 + k];
        float v = 0.f;
        for (int t = 0; t < T_; t++) {
            float lp = 0.f;
            #pragma unroll
            for (int k = 0; k < KK_; k++) lp += sCl[k*64 + t]*xk[k];
            v += (lp - v)*0.5f;
            bool s = (v >= 1.0f); if (s) v = 0.f;
            u32 bal = __ballot_sync(0xffffffffu, s);
            if ((tid & 31) == 0) sbal[t*8 + (tid >> 5)] = bal;
        }
    }
    __syncthreads();
    if (tid < 256) {
        int bnl = tid >> 7, rr = tid & 127, t = rr >> 1, h = rr & 1;
        int g = bnl*4 + 2*h;
        u64 bits = (u64)sbal[t*8 + g] | ((u64)sbal[t*8 + g + 1] << 32);
        int bn = bn0 + bnl, b = bn >> 6, n = bn & 63;
        size_t idx = (((size_t)t*B_ + b)*H_ + h)*N_ + n;
        if (gy == 0) g_kbits[idx] = bits; else g_vbits[idx] = bits;
    }
}

// ---------------- K3: popcount attention -> g_o --------------------------------
__global__ __launch_bounds__(256) void k_attn() {
    __shared__ u64 qb[128], kb[128], vb[128];
    __shared__ float vf[8192];
    int tb = blockIdx.x, t = tb >> 6, b = tb & 63;
    int tid = threadIdx.x;
    size_t base = ((size_t)t*B_ + b)*H_*N_;
    if (tid < 128) { qb[tid] = g_qbits[base + tid]; kb[tid] = g_kbits[base + tid]; vb[tid] = g_vbits[base + tid]; }
    __syncthreads();
    for (int i = tid; i < 8192; i += 256) vf[i] = (float)((vb[i >> 6] >> (i & 63)) & 1ull);
    __syncthreads();
    int n = tid >> 2, dg = tid & 3, h = dg >> 1, half = dg & 1;
    u64 qn = qb[h*64 + n];
    u64 acc[16];
    #pragma unroll
    for (int j = 0; j < 16; j++) acc[j] = 0ull;
    #pragma unroll 4
    for (int m = 0; m < 64; m++) {
        float c = (float)__popcll(qn & kb[h*64 + m]);
        u64 cd = pk2(c, c);
        const float* vr = vf + (h*64 + m)*64 + half*32;
        #pragma unroll
        for (int j = 0; j < 16; j++) ffma2(acc[j], cd, *(const u64*)(vr + 2*j));
    }
    float* op = g_o + (((size_t)t*B_ + b)*N_ + n)*128 + h*64 + half*32;
    #pragma unroll
    for (int j = 0; j < 16; j++) {
        float2 f = up2(acc[j]);
        *(float2*)(op + 2*j) = make_float2(f.x*0.125f, f.y*0.125f);
    }
}

// ---------------- K6: xg @ W1-half(by gy) + LIF -> m1 bitmaps ------------------
#define SMEM_W1 (131072 + 2048 + 2048)
__global__ __launch_bounds__(1024, 1) void k_w1(const float* __restrict__ x,
                                                const float* __restrict__ W1) {
    extern __shared__ float sm[];
    u64* As2 = (u64*)sm;
    u64* Ws2 = As2 + 8192;
    float* Cs = sm;
    u64* sab = (u64*)(sm + SBASE);     // 256 u64
    u32* sbal = (u32*)(sm + SBASE + 512);
    int tid = threadIdx.x, bn0 = blockIdx.x*2, gy = blockIdx.y;

    if (tid < 256) {
        int bnl = tid >> 7, rr = tid & 127, t = rr >> 1, ww = rr & 1;
        int bn = bn0 + bnl, b = bn >> 6, n = bn & 63;
        sab[bnl*128 + t*2 + ww] = g_abits[(((size_t)t*B_ + b)*N_ + n)*H_ + ww];
    }
    build_W(Ws2, W1, 256, gy*128, tid);
    __syncthreads();

    {   // A pack: xg = x * (1 - attn_spk)
        int row = tid >> 3, kq0 = tid & 7;
        int bnl = row >> 6, t = row & 63;
        const float4* xp = (const float4*)(x + (size_t)(bn0 + bnl)*128 + (size_t)t*PLANE);
        #pragma unroll
        for (int i = 0; i < 4; i++) {
            int kqq = kq0 + 8*i;
            float4 v = xp[kqq];
            u64 ab = sab[bnl*128 + t*2 + (kqq >> 4)];
            int sh = (4*kqq) & 63;
            float g0 = ((ab >> sh) & 1ull) ? 0.f : 1.f;
            float g1 = ((ab >> (sh+1)) & 1ull) ? 0.f : 1.f;
            float g2 = ((ab >> (sh+2)) & 1ull) ? 0.f : 1.f;
            float g3 = ((ab >> (sh+3)) & 1ull) ? 0.f : 1.f;
            As2[(2*kqq)*128 + row]   = pk2(v.x*g0, v.y*g1);
            As2[(2*kqq+1)*128 + row] = pk2(v.z*g2, v.w*g3);
        }
    }
    __syncthreads();

    ZACC;
    int w = tid >> 5, lane = tid & 31;
    int rowg = w >> 1, c0 = (w & 1)*64 + lane*2;
    gemm_core(As2, Ws2, acc, rowg, c0);
    __syncthreads();
    store_c(Cs, acc, rowg, c0);
    __syncthreads();

    if (tid < 256) {
        int bnl = tid >> 7, col = tid & 127;
        float v = 0.f;
        for (int t = 0; t < T_; t++) {
            float c = Cs[(bnl*64 + t)*128 + col];
            v += (c - v)*0.5f;
            bool s = (v >= 1.0f); if (s) v = 0.f;
            u32 bal = __ballot_sync(0xffffffffu, s);
            if ((tid & 31) == 0) sbal[t*8 + (tid >> 5)] = bal;
        }
    }
    __syncthreads();
    if (tid < 256) {
        int bnl = tid >> 7, rr = tid & 127, t = rr >> 1, h = rr & 1;
        int g = bnl*4 + 2*h;
        u64 bits = (u64)sbal[t*8 + g] | ((u64)sbal[t*8 + g + 1] << 32);
        int bn = bn0 + bnl, b = bn >> 6, n = bn & 63;
        g_m1bits[(((size_t)t*B_ + b)*N_ + n)*4 + gy*2 + h] = bits;
    }
}

// ---------------- K7: sparse m1 @ W2 + LIF + final gated output ---------------
#define SMEM_W2 (256*128*4 + 1024*8 + 512*8)
__global__ __launch_bounds__(512, 1) void k_w2(const float* __restrict__ x,
                                               const float* __restrict__ W2,
                                               float* __restrict__ out) {
    extern __shared__ float sm[];
    float* W2s = sm;
    u64* sm1 = (u64*)(sm + 256*128);
    u64* sab = sm1 + 1024;
    int tid = threadIdx.x, bn0 = blockIdx.x*4;
    int grp = tid >> 7, d = tid & 127;

    {
        const float4* Wg = (const float4*)W2;
        float4* Wm = (float4*)W2s;
        #pragma unroll
        for (int i = tid; i < 8192; i += 512) Wm[i] = Wg[i];
    }
    #pragma unroll
    for (int i = tid; i < 1024; i += 512) {
        int g = i >> 8, rr = i & 255, t = rr >> 2, ww = rr & 3;
        int bn = bn0 + g, b = bn >> 6, n = bn & 63;
        sm1[i] = g_m1bits[(((size_t)t*B_ + b)*N_ + n)*4 + ww];
    }
    {
        int g = tid >> 7, rr = tid & 127, t = rr >> 1, ww = rr & 1;
        int bn = bn0 + g, b = bn >> 6, n = bn & 63;
        sab[tid] = g_abits[(((size_t)t*B_ + b)*N_ + n)*H_ + ww];
    }
    __syncthreads();

    int bn = bn0 + grp;
    const u64* mrow = sm1 + grp*256;
    const u64* arow = sab + grp*128;
    float v = 0.f;
    for (int t = 0; t < T_; t++) {
        float a0 = 0.f, a1 = 0.f;
        #pragma unroll
        for (int ww = 0; ww < 4; ww += 2) {
            u64 bb = mrow[t*4 + ww];
            while (bb) { int k2 = __ffsll((long long)bb) - 1; bb &= bb - 1ull; a0 += W2s[(ww*64 + k2)*128 + d]; }
            u64 bc = mrow[t*4 + ww + 1];
            while (bc) { int k2 = __ffsll((long long)bc) - 1; bc &= bc - 1ull; a1 += W2s[((ww + 1)*64 + k2)*128 + d]; }
        }
        float a = a0 + a1;
        v += (a - v)*0.5f;
        bool s = (v >= 1.0f); if (s) v = 0.f;
        u32 ag = (u32)((arow[t*2 + (d >> 6)] >> (d & 63)) & 1ull);
        size_t off = (size_t)t*PLANE + (size_t)bn*128 + d;
        out[off] = (s || ag) ? 0.f : x[off];
    }
}

// ---------------- launch ------------------------------------------------------
extern "C" void kernel_launch(void* const* d_in, const int* in_sizes, int n_in,
                              void* d_out, int out_size) {
    const float* x  = (const float*)d_in[0];
    const float* mx = (const float*)d_in[1];
    const float* Wq = (const float*)d_in[2];
    const float* Wk = (const float*)d_in[3];
    const float* Wv = (const float*)d_in[4];
    const float* Wo = (const float*)d_in[5];
    const float* W1 = (const float*)d_in[6];
    const float* W2 = (const float*)d_in[7];
    float* out = (float*)d_out;

    static float* s_o = nullptr;
    if (!s_o) { void* p = nullptr; cudaGetSymbolAddress(&p, g_o); s_o = (float*)p; }
    static bool s_attr = false;
    if (!s_attr) {
        cudaFuncSetAttribute(k_g128, cudaFuncAttributeMaxDynamicSharedMemorySize, SMEM_G);
        cudaFuncSetAttribute(k_kv,   cudaFuncAttributeMaxDynamicSharedMemorySize, SMEM_KV);
        cudaFuncSetAttribute(k_w1,   cudaFuncAttributeMaxDynamicSharedMemorySize, SMEM_W1);
        cudaFuncSetAttribute(k_w2,   cudaFuncAttributeMaxDynamicSharedMemorySize, SMEM_W2);
        s_attr = true;
    }

    k_dct<<<1, dim3(T_, KK_)>>>();                            // 1
    k_g128<<<2048, 1024, SMEM_G>>>(x, Wq, 0);                 // 2
    k_nop<<<1, 32>>>();                                       // 3
    k_kv<<<dim3(2048, 2), 1024, SMEM_KV>>>(x, mx, Wk, Wv);    // 4 <- profiled
    k_attn<<<T_*B_, 256>>>();                                 // 5
    k_g128<<<2048, 1024, SMEM_G>>>(s_o, Wo, 1);               // 6
    k_w1<<<dim3(2048, 2), 1024, SMEM_W1>>>(x, W1);            // 7
    k_w2<<<1024, 512, SMEM_W2>>>(x, W2, out);                 // 8
}

// round 13
// speedup vs baseline: 1.1828x; 1.1828x over previous
#include <cuda_runtime.h>
#include <math.h>

#define T_ 64
#define B_ 64
#define N_ 64
#define H_ 2
#define KK_ 16
#define PLANE (64*64*128)
#define RP 132
#define CP 130
#define ASF (128*RP)        // 16896 floats
#define WEND (ASF + 16384)  // 33280 floats

typedef unsigned long long u64;
typedef unsigned int u32;

__device__ float g_Cl[KK_*T_];
__device__ u64 g_qbits[(size_t)T_*B_*H_*N_];
__device__ u64 g_kbits[(size_t)T_*B_*H_*N_];
__device__ u64 g_vbits[(size_t)T_*B_*H_*N_];
__device__ u64 g_abits[(size_t)T_*B_*N_*H_];
__device__ u64 g_m1bits[(size_t)T_*B_*N_*4];
__device__ float g_o[(size_t)T_*B_*N_*128];

namespace {
struct ModuleWarm { ModuleWarm() { void* p = nullptr; (void)cudaGetSymbolAddress(&p, g_qbits); } };
static ModuleWarm s_mw;
}

__device__ __forceinline__ void ffma2(u64 &d, u64 a, u64 b) {
    asm("fma.rn.f32x2 %0, %1, %2, %0;" : "+l"(d) : "l"(a), "l"(b));
}
__device__ __forceinline__ u64 pk2(float lo, float hi) {
    u64 r; asm("mov.b64 %0, {%1,%2};" : "=l"(r) : "f"(lo), "f"(hi)); return r;
}
__device__ __forceinline__ float2 up2(u64 v) {
    float2 f; asm("mov.b64 {%0,%1}, %2;" : "=f"(f.x), "=f"(f.y) : "l"(v)); return f;
}

__global__ void k_dct() {
    int t = threadIdx.x, k = threadIdx.y;
    double c = cos(M_PI * ((double)t + 0.5) * (double)k / 64.0) * sqrt(2.0 / 64.0);
    if (k == 0) c *= (1.0 / sqrt(2.0));
    g_Cl[k*T_ + t] = (float)c;
}

// ---- GEMM: 128 rows (2bn x 64t) x 128 cols, K=128, register double-buffer ----
// As [k][row] pitch RP (A loads warp-broadcast); Ws [k][128] (contiguous float4).
// 512 thr = 16 warps: warp w = rows w*8..w*8+7; lane = cols lane*4..+3.
__device__ __forceinline__ void gemm_pf(const float* __restrict__ As,
                                        const float* __restrict__ Ws,
                                        u64 (&acc)[4][4], int w, int lane) {
    const float* ar = As + w*8;
    const float* wr = Ws + lane*4;
    ulonglong2 pa = *(const ulonglong2*)ar;
    ulonglong2 pb = *(const ulonglong2*)(ar + 4);
    float4 wc = *(const float4*)wr;
    #pragma unroll 4
    for (int k = 0; k < 128; k++) {
        int kn = (k + 1) & 127;
        ulonglong2 pan = *(const ulonglong2*)(ar + kn*RP);
        ulonglong2 pbn = *(const ulonglong2*)(ar + kn*RP + 4);
        float4 wn = *(const float4*)(wr + kn*128);
        u64 w0 = pk2(wc.x, wc.x), w1 = pk2(wc.y, wc.y);
        u64 w2 = pk2(wc.z, wc.z), w3 = pk2(wc.w, wc.w);
        ffma2(acc[0][0], pa.x, w0); ffma2(acc[0][1], pa.x, w1);
        ffma2(acc[0][2], pa.x, w2); ffma2(acc[0][3], pa.x, w3);
        ffma2(acc[1][0], pa.y, w0); ffma2(acc[1][1], pa.y, w1);
        ffma2(acc[1][2], pa.y, w2); ffma2(acc[1][3], pa.y, w3);
        ffma2(acc[2][0], pb.x, w0); ffma2(acc[2][1], pb.x, w1);
        ffma2(acc[2][2], pb.x, w2); ffma2(acc[2][3], pb.x, w3);
        ffma2(acc[3][0], pb.y, w0); ffma2(acc[3][1], pb.y, w1);
        ffma2(acc[3][2], pb.y, w2); ffma2(acc[3][3], pb.y, w3);
        pa = pan; pb = pbn; wc = wn;
    }
}

__device__ __forceinline__ void store_c(float* Cs, u64 (&acc)[4][4], int w, int lane) {
    #pragma unroll
    for (int j = 0; j < 4; j++) {
        float* cc = Cs + (lane*4 + j)*CP + w*8;
        #pragma unroll
        for (int p = 0; p < 4; p++) *(u64*)(cc + 2*p) = acc[p][j];
    }
}
#define ZACC u64 acc[4][4]; _Pragma("unroll") for (int i_ = 0; i_ < 4; i_++) { acc[i_][0]=0ull; acc[i_][1]=0ull; acc[i_][2]=0ull; acc[i_][3]=0ull; }

__device__ __forceinline__ void lif_bits(const float* Cs, u32* sbal, int tid,
                                         int bn0, u64* dst_q, u64* dst_a, int mode) {
    if (tid < 256) {
        int bnl = tid >> 7, col = tid & 127;
        const float* cc = Cs + col*CP + bnl*64;
        float v = 0.f;
        for (int t = 0; t < T_; t++) {
            float c = cc[t];
            v += (c - v)*0.5f;
            bool s = (v >= 1.0f); if (s) v = 0.f;
            u32 bal = __ballot_sync(0xffffffffu, s);
            if ((tid & 31) == 0) sbal[t*8 + (tid >> 5)] = bal;
        }
    }
    __syncthreads();
    if (tid < 256) {
        int bnl = tid >> 7, rr = tid & 127, t = rr >> 1, h = rr & 1;
        int g = bnl*4 + 2*h;
        u64 bits = (u64)sbal[t*8 + g] | ((u64)sbal[t*8 + g + 1] << 32);
        int bn = bn0 + bnl, b = bn >> 6, n = bn & 63;
        if (mode == 0) dst_q[(((size_t)t*B_ + b)*H_ + h)*N_ + n] = bits;
        else           dst_a[(((size_t)t*B_ + b)*N_ + n)*H_ + h] = bits;
    }
}

// ---------------- K1/K5: src @ W(128x128) + LIF ------------------------------
#define SMEM_G ((WEND + 512)*4)
__global__ __launch_bounds__(512, 1) void k_g128(const float* __restrict__ src,
                                                 const float* __restrict__ W, int mode) {
    extern __shared__ float sm[];
    float* As = sm; float* Ws = sm + ASF; float* Cs = sm;
    u32* sbal = (u32*)(sm + WEND);
    int tid = threadIdx.x, bn0 = blockIdx.x*2;
    int w = tid >> 5, lane = tid & 31;

    {   // A build
        int k = tid & 127, q4 = tid >> 7, bnl = q4 >> 1, t0 = (q4 & 1)*32;
        const float* sp = src + (size_t)(bn0 + bnl)*128 + k;
        float* ad = As + k*RP + bnl*64;
        #pragma unroll 8
        for (int i = 0; i < 32; i++) { int t = t0 + i; ad[t] = sp[(size_t)t*PLANE]; }
    }
    {
        const float4* Wg = (const float4*)W;
        float4* Wm = (float4*)Ws;
        #pragma unroll
        for (int i = tid; i < 4096; i += 512) Wm[i] = Wg[i];
    }
    __syncthreads();
    ZACC;
    gemm_pf(As, Ws, acc, w, lane);
    __syncthreads();
    store_c(Cs, acc, w, lane);
    __syncthreads();
    lif_bits(Cs, sbal, tid, bn0, g_qbits, g_abits, mode);
}

// ---------------- K2: (x*mx) @ (Wk|Wv by gy) + lowpass + LIF ------------------
#define SMEM_KV ((WEND + 1024 + 512)*4)
__global__ __launch_bounds__(512, 1) void k_kv(const float* __restrict__ x,
                                               const float* __restrict__ mx,
                                               const float* __restrict__ Wk,
                                               const float* __restrict__ Wv) {
    extern __shared__ float sm[];
    float* As = sm; float* Ws = sm + ASF; float* Cs = sm;
    float* sCl = sm + WEND;
    u32* sbal = (u32*)(sm + WEND + 1024);
    int tid = threadIdx.x, bn0 = blockIdx.x*2, gy = blockIdx.y;
    int w = tid >> 5, lane = tid & 31;

    {   // A build: raw x*mx (lowpass commutes with the feature GEMM)
        int k = tid & 127, q4 = tid >> 7, bnl = q4 >> 1, t0 = (q4 & 1)*32;
        int bn = bn0 + bnl, b = bn >> 6, n = bn & 63;
        const float* xp = x + (size_t)bn*128 + k;
        const float* mp = mx + ((size_t)n*B_ + b)*T_*128 + k;
        float* ad = As + k*RP + bnl*64;
        #pragma unroll 8
        for (int i = 0; i < 32; i++) {
            int t = t0 + i;
            float m = mp[(size_t)t*128];
            m = 0.05f*m + 0.95f*m;
            ad[t] = xp[(size_t)t*PLANE] * m;
        }
    }
    {
        const float4* Wg = (const float4*)(gy ? Wv : Wk);
        float4* Wm = (float4*)Ws;
        #pragma unroll
        for (int i = tid; i < 4096; i += 512) Wm[i] = Wg[i];
    }
    for (int i = tid; i < 1024; i += 512) sCl[i] = g_Cl[i];
    __syncthreads();
    ZACC;
    gemm_pf(As, Ws, acc, w, lane);
    __syncthreads();
    store_c(Cs, acc, w, lane);
    __syncthreads();

    if (tid < 256) {   // DCT lowpass along t + LIF
        int bnl = tid >> 7, col = tid & 127;
        const float* cc = Cs + col*CP + bnl*64;
        float ca[32], Xk[KK_];
        #pragma unroll
        for (int i = 0; i < 32; i++) ca[i] = cc[i];
        #pragma unroll
        for (int k = 0; k < KK_; k++) {
            float s = 0.f;
            #pragma unroll
            for (int i = 0; i < 32; i++) s += sCl[k*64 + i]*ca[i];
            Xk[k] = s;
        }
        #pragma unroll
        for (int i = 0; i < 32; i++) ca[i] = cc[32 + i];
        #pragma unroll
        for (int k = 0; k < KK_; k++) {
            float s = Xk[k];
            #pragma unroll
            for (int i = 0; i < 32; i++) s += sCl[k*64 + 32 + i]*ca[i];
            Xk[k] = s;
        }
        float v = 0.f;
        for (int t = 0; t < T_; t++) {
            float lp = 0.f;
            #pragma unroll
            for (int k = 0; k < KK_; k++) lp += sCl[k*64 + t]*Xk[k];
            v += (lp - v)*0.5f;
            bool s = (v >= 1.0f); if (s) v = 0.f;
            u32 bal = __ballot_sync(0xffffffffu, s);
            if ((tid & 31) == 0) sbal[t*8 + (tid >> 5)] = bal;
        }
    }
    __syncthreads();
    if (tid < 256) {
        int bnl = tid >> 7, rr = tid & 127, t = rr >> 1, h = rr & 1;
        int g = bnl*4 + 2*h;
        u64 bits = (u64)sbal[t*8 + g] | ((u64)sbal[t*8 + g + 1] << 32);
        int bn = bn0 + bnl, b = bn >> 6, n = bn & 63;
        size_t idx = (((size_t)t*B_ + b)*H_ + h)*N_ + n;
        if (gy == 0) g_kbits[idx] = bits; else g_vbits[idx] = bits;
    }
}

// ---------------- K3: popcount attention -> g_o --------------------------------
__global__ __launch_bounds__(256) void k_attn() {
    __shared__ u64 qb[128], kb[128], vb[128];
    __shared__ float vf[8192];
    int tb = blockIdx.x, t = tb >> 6, b = tb & 63;
    int tid = threadIdx.x;
    size_t base = ((size_t)t*B_ + b)*H_*N_;
    if (tid < 128) { qb[tid] = g_qbits[base + tid]; kb[tid] = g_kbits[base + tid]; vb[tid] = g_vbits[base + tid]; }
    __syncthreads();
    for (int i = tid; i < 8192; i += 256) vf[i] = (float)((vb[i >> 6] >> (i & 63)) & 1ull);
    __syncthreads();
    int n = tid >> 2, dg = tid & 3, h = dg >> 1, half = dg & 1;
    u64 qn = qb[h*64 + n];
    u64 acc[16];
    #pragma unroll
    for (int j = 0; j < 16; j++) acc[j] = 0ull;
    #pragma unroll 4
    for (int m = 0; m < 64; m++) {
        float c = (float)__popcll(qn & kb[h*64 + m]);
        u64 cd = pk2(c, c);
        const float* vr = vf + (h*64 + m)*64 + half*32;
        #pragma unroll
        for (int j = 0; j < 16; j++) ffma2(acc[j], cd, *(const u64*)(vr + 2*j));
    }
    float* op = g_o + (((size_t)t*B_ + b)*N_ + n)*128 + h*64 + half*32;
    #pragma unroll
    for (int j = 0; j < 16; j++) {
        float2 f = up2(acc[j]);
        *(float2*)(op + 2*j) = make_float2(f.x*0.125f, f.y*0.125f);  // 1/8 exact
    }
}

// ---------------- K6: xg @ W1-half(gy) + LIF -> m1 bitmaps ---------------------
#define SMEM_W1 ((WEND + 512 + 512)*4)
__global__ __launch_bounds__(512, 1) void k_w1(const float* __restrict__ x,
                                               const float* __restrict__ W1) {
    extern __shared__ float sm[];
    float* As = sm; float* Ws = sm + ASF; float* Cs = sm;
    u64* sab = (u64*)(sm + WEND);
    u32* sbal = (u32*)(sm + WEND + 512);
    int tid = threadIdx.x, bn0 = blockIdx.x*2, gy = blockIdx.y;
    int w = tid >> 5, lane = tid & 31;

    if (tid < 256) {
        int bnl = tid >> 7, rr = tid & 127, t = rr >> 1, ww = rr & 1;
        int bn = bn0 + bnl, b = bn >> 6, n = bn & 63;
        sab[bnl*128 + t*2 + ww] = g_abits[(((size_t)t*B_ + b)*N_ + n)*H_ + ww];
    }
    {   // W half copy: cols gy*128..+127 of W1 [128][256]
        const float4* Wg = (const float4*)W1;
        float4* Wm = (float4*)Ws;
        #pragma unroll
        for (int i = tid; i < 4096; i += 512) {
            int row = i >> 5, cq = i & 31;
            Wm[i] = Wg[row*64 + gy*32 + cq];
        }
    }
    __syncthreads();
    {   // A build: xg = x * (1 - attn_spk)
        int k = tid & 127, q4 = tid >> 7, bnl = q4 >> 1, t0 = (q4 & 1)*32;
        const float* xp = x + (size_t)(bn0 + bnl)*128 + k;
        float* ad = As + k*RP + bnl*64;
        #pragma unroll 8
        for (int i = 0; i < 32; i++) {
            int t = t0 + i;
            u64 ab = sab[bnl*128 + t*2 + (k >> 6)];
            float gt = ((ab >> (k & 63)) & 1ull) ? 0.f : 1.f;
            ad[t] = xp[(size_t)t*PLANE] * gt;
        }
    }
    __syncthreads();
    ZACC;
    gemm_pf(As, Ws, acc, w, lane);
    __syncthreads();
    store_c(Cs, acc, w, lane);
    __syncthreads();

    if (tid < 256) {
        int bnl = tid >> 7, col = tid & 127;
        const float* cc = Cs + col*CP + bnl*64;
        float v = 0.f;
        for (int t = 0; t < T_; t++) {
            float c = cc[t];
            v += (c - v)*0.5f;
            bool s = (v >= 1.0f); if (s) v = 0.f;
            u32 bal = __ballot_sync(0xffffffffu, s);
            if ((tid & 31) == 0) sbal[t*8 + (tid >> 5)] = bal;
        }
    }
    __syncthreads();
    if (tid < 256) {
        int bnl = tid >> 7, rr = tid & 127, t = rr >> 1, h = rr & 1;
        int g = bnl*4 + 2*h;
        u64 bits = (u64)sbal[t*8 + g] | ((u64)sbal[t*8 + g + 1] << 32);
        int bn = bn0 + bnl, b = bn >> 6, n = bn & 63;
        g_m1bits[(((size_t)t*B_ + b)*N_ + n)*4 + gy*2 + h] = bits;
    }
}

// ---------------- K7: sparse m1 @ W2 + LIF + final gated output ---------------
#define SMEM_W2 (256*128*4 + 1024*8 + 512*8)
__global__ __launch_bounds__(512, 1) void k_w2(const float* __restrict__ x,
                                               const float* __restrict__ W2,
                                               float* __restrict__ out) {
    extern __shared__ float sm[];
    float* W2s = sm;
    u64* sm1 = (u64*)(sm + 256*128);
    u64* sab = sm1 + 1024;
    int tid = threadIdx.x, bn0 = blockIdx.x*4;
    int grp = tid >> 7, d = tid & 127;

    {
        const float4* Wg = (const float4*)W2;
        float4* Wm = (float4*)W2s;
        #pragma unroll
        for (int i = tid; i < 8192; i += 512) Wm[i] = Wg[i];
    }
    #pragma unroll
    for (int i = tid; i < 1024; i += 512) {
        int g = i >> 8, rr = i & 255, t = rr >> 2, ww = rr & 3;
        int bn = bn0 + g, b = bn >> 6, n = bn & 63;
        sm1[i] = g_m1bits[(((size_t)t*B_ + b)*N_ + n)*4 + ww];
    }
    {
        int g = tid >> 7, rr = tid & 127, t = rr >> 1, ww = rr & 1;
        int bn = bn0 + g, b = bn >> 6, n = bn & 63;
        sab[tid] = g_abits[(((size_t)t*B_ + b)*N_ + n)*H_ + ww];
    }
    __syncthreads();

    int bn = bn0 + grp;
    const u64* mrow = sm1 + grp*256;
    const u64* arow = sab + grp*128;
    float v = 0.f;
    for (int t = 0; t < T_; t++) {
        float a0 = 0.f, a1 = 0.f;
        #pragma unroll
        for (int ww = 0; ww < 4; ww += 2) {
            u64 bb = mrow[t*4 + ww];
            while (bb) { int k2 = __ffsll((long long)bb) - 1; bb &= bb - 1ull; a0 += W2s[(ww*64 + k2)*128 + d]; }
            u64 bc = mrow[t*4 + ww + 1];
            while (bc) { int k2 = __ffsll((long long)bc) - 1; bc &= bc - 1ull; a1 += W2s[((ww + 1)*64 + k2)*128 + d]; }
        }
        float a = a0 + a1;
        v += (a - v)*0.5f;
        bool s = (v >= 1.0f); if (s) v = 0.f;
        u32 ag = (u32)((arow[t*2 + (d >> 6)] >> (d & 63)) & 1ull);
        size_t off = (size_t)t*PLANE + (size_t)bn*128 + d;
        out[off] = (s || ag) ? 0.f : x[off];
    }
}

// ---------------- launch ------------------------------------------------------
extern "C" void kernel_launch(void* const* d_in, const int* in_sizes, int n_in,
                              void* d_out, int out_size) {
    const float* x  = (const float*)d_in[0];
    const float* mx = (const float*)d_in[1];
    const float* Wq = (const float*)d_in[2];
    const float* Wk = (const float*)d_in[3];
    const float* Wv = (const float*)d_in[4];
    const float* Wo = (const float*)d_in[5];
    const float* W1 = (const float*)d_in[6];
    const float* W2 = (const float*)d_in[7];
    float* out = (float*)d_out;

    static float* s_o = nullptr;
    if (!s_o) { void* p = nullptr; cudaGetSymbolAddress(&p, g_o); s_o = (float*)p; }
    static bool s_attr = false;
    if (!s_attr) {
        cudaFuncSetAttribute(k_g128, cudaFuncAttributeMaxDynamicSharedMemorySize, SMEM_G);
        cudaFuncSetAttribute(k_kv,   cudaFuncAttributeMaxDynamicSharedMemorySize, SMEM_KV);
        cudaFuncSetAttribute(k_w1,   cudaFuncAttributeMaxDynamicSharedMemorySize, SMEM_W1);
        cudaFuncSetAttribute(k_w2,   cudaFuncAttributeMaxDynamicSharedMemorySize, SMEM_W2);
        s_attr = true;
    }

    // slot 4 = k_attn (the one ncu captures this round)
    k_dct<<<1, dim3(T_, KK_)>>>();                           // 1
    k_g128<<<2048, 512, SMEM_G>>>(x, Wq, 0);                 // 2
    k_kv<<<dim3(2048, 2), 512, SMEM_KV>>>(x, mx, Wk, Wv);    // 3
    k_attn<<<T_*B_, 256>>>();                                // 4 <- profiled
    k_g128<<<2048, 512, SMEM_G>>>(s_o, Wo, 1);               // 5
    k_w1<<<dim3(2048, 2), 512, SMEM_W1>>>(x, W1);            // 6
    k_w2<<<1024, 512, SMEM_W2>>>(x, W2, out);                // 7
}

// round 14
// speedup vs baseline: 1.7990x; 1.5209x over previous
#include <cuda_runtime.h>
#include <math.h>

#define T_ 64
#define B_ 64
#define N_ 64
#define H_ 2
#define KK_ 16
#define PLANE (64*64*128)
#define RP 132
#define CP 130
#define ASF (128*RP)          // 16896 floats
#define GW_END (ASF + 16384)  // g128: Ws end = 33280
#define KW_END (ASF + 32768)  // kv/w1: Ws end = 49664

typedef unsigned long long u64;
typedef unsigned int u32;

__device__ float g_Cl[KK_*T_];
__device__ u64 g_qbits[(size_t)T_*B_*H_*N_];
__device__ u64 g_kbits[(size_t)T_*B_*H_*N_];
__device__ u64 g_vbits[(size_t)T_*B_*H_*N_];
__device__ u64 g_abits[(size_t)T_*B_*N_*H_];
__device__ u64 g_m1bits[(size_t)T_*B_*N_*4];
__device__ float g_o[(size_t)T_*B_*N_*128];

namespace {
struct ModuleWarm { ModuleWarm() { void* p = nullptr; (void)cudaGetSymbolAddress(&p, g_qbits); } };
static ModuleWarm s_mw;
}

__device__ __forceinline__ void ffma2(u64 &d, u64 a, u64 b) {
    asm("fma.rn.f32x2 %0, %1, %2, %0;" : "+l"(d) : "l"(a), "l"(b));
}
__device__ __forceinline__ u64 pk2(float lo, float hi) {
    u64 r; asm("mov.b64 %0, {%1,%2};" : "=l"(r) : "f"(lo), "f"(hi)); return r;
}
__device__ __forceinline__ float2 up2(u64 v) {
    float2 f; asm("mov.b64 {%0,%1}, %2;" : "=f"(f.x), "=f"(f.y) : "l"(v)); return f;
}

__global__ void k_dct() {
    int t = threadIdx.x, k = threadIdx.y;
    double c = cos(M_PI * ((double)t + 0.5) * (double)k / 64.0) * sqrt(2.0 / 64.0);
    if (k == 0) c *= (1.0 / sqrt(2.0));
    g_Cl[k*T_ + t] = (float)c;
}

// ---- R9 GEMM: 128 rows (2bn x 64t) x NH*128 cols, K=128 ----------------------
// As [k][row] pitch RP (warp-broadcast A); Ws [k][NH*128] (contiguous float4 W).
// 512 thr = 16 warps: warp w = rows w*8..+7; lane = cols h*128+lane*4..+3.
template<int NH>
__device__ __forceinline__ void gemm_bc(const float* __restrict__ As,
                                        const float* __restrict__ Ws,
                                        u64 (&acc)[4][NH*4], int w, int lane) {
    #pragma unroll 2
    for (int k = 0; k < 128; k++) {
        const float* ar = As + k*RP + w*8;
        ulonglong2 pa = *(const ulonglong2*)ar;
        ulonglong2 pb = *(const ulonglong2*)(ar + 4);
        const float* wr = Ws + k*(NH*128) + lane*4;
        #pragma unroll
        for (int h = 0; h < NH; h++) {
            float4 w4 = *(const float4*)(wr + h*128);
            u64 w0 = pk2(w4.x, w4.x), w1 = pk2(w4.y, w4.y);
            u64 w2 = pk2(w4.z, w4.z), w3 = pk2(w4.w, w4.w);
            int j = h*4;
            ffma2(acc[0][j+0], pa.x, w0); ffma2(acc[0][j+1], pa.x, w1);
            ffma2(acc[0][j+2], pa.x, w2); ffma2(acc[0][j+3], pa.x, w3);
            ffma2(acc[1][j+0], pa.y, w0); ffma2(acc[1][j+1], pa.y, w1);
            ffma2(acc[1][j+2], pa.y, w2); ffma2(acc[1][j+3], pa.y, w3);
            ffma2(acc[2][j+0], pb.x, w0); ffma2(acc[2][j+1], pb.x, w1);
            ffma2(acc[2][j+2], pb.x, w2); ffma2(acc[2][j+3], pb.x, w3);
            ffma2(acc[3][j+0], pb.y, w0); ffma2(acc[3][j+1], pb.y, w1);
            ffma2(acc[3][j+2], pb.y, w2); ffma2(acc[3][j+3], pb.y, w3);
        }
    }
}

// Cs column-major, pitch CP=130 (128 rows fit, no aliasing; u64 aligned)
template<int NH>
__device__ __forceinline__ void store_bc(float* Cs, u64 (&acc)[4][NH*4], int w, int lane) {
    #pragma unroll
    for (int h = 0; h < NH; h++)
        #pragma unroll
        for (int j = 0; j < 4; j++) {
            float* cc = Cs + (h*128 + lane*4 + j)*CP + w*8;
            #pragma unroll
            for (int p = 0; p < 4; p++) *(u64*)(cc + 2*p) = acc[p][h*4 + j];
        }
}

// ---------------- K1/K5: src @ W(128x128) + LIF -> q / attn-gate bits ----------
#define SMEM_G ((GW_END + 512)*4)
__global__ __launch_bounds__(512, 1) void k_g128(const float* __restrict__ src,
                                                 const float* __restrict__ W, int mode) {
    extern __shared__ float sm[];
    float* As = sm; float* Ws = sm + ASF; float* Cs = sm;
    u32* sbal = (u32*)(sm + GW_END);
    int tid = threadIdx.x, bn0 = blockIdx.x*2;
    int w = tid >> 5, lane = tid & 31;

    {   // A build
        int k = tid & 127, q4 = tid >> 7, bnl = q4 >> 1, t0 = (q4 & 1)*32;
        const float* sp = src + (size_t)(bn0 + bnl)*128 + k;
        float* ad = As + k*RP + bnl*64;
        #pragma unroll 8
        for (int i = 0; i < 32; i++) { int t = t0 + i; ad[t] = sp[(size_t)t*PLANE]; }
    }
    {
        const float4* Wg = (const float4*)W;
        float4* Wm = (float4*)Ws;
        #pragma unroll
        for (int i = tid; i < 4096; i += 512) Wm[i] = Wg[i];
    }
    __syncthreads();
    u64 acc[4][4];
    #pragma unroll
    for (int p = 0; p < 4; p++) { acc[p][0]=0; acc[p][1]=0; acc[p][2]=0; acc[p][3]=0; }
    gemm_bc<1>(As, Ws, acc, w, lane);
    __syncthreads();
    store_bc<1>(Cs, acc, w, lane);
    __syncthreads();

    if (tid < 256) {
        int bnl = tid >> 7, col = tid & 127;
        const float* cc = Cs + col*CP + bnl*64;
        float v = 0.f;
        for (int t = 0; t < T_; t++) {
            float c = cc[t];
            v += (c - v)*0.5f;
            bool s = (v >= 1.0f); if (s) v = 0.f;
            u32 bal = __ballot_sync(0xffffffffu, s);
            if ((tid & 31) == 0) sbal[t*8 + (tid >> 5)] = bal;
        }
    }
    __syncthreads();
    if (tid < 256) {
        int bnl = tid >> 7, rr = tid & 127, t = rr >> 1, h = rr & 1;
        int g = bnl*4 + 2*h;
        u64 bits = (u64)sbal[t*8 + g] | ((u64)sbal[t*8 + g + 1] << 32);
        int bn = bn0 + bnl, b = bn >> 6, n = bn & 63;
        if (mode == 0) g_qbits[(((size_t)t*B_ + b)*H_ + h)*N_ + n] = bits;
        else           g_abits[(((size_t)t*B_ + b)*N_ + n)*H_ + h] = bits;
    }
}

// ---------------- K2: (x*mx) @ [Wk|Wv] fused + lowpass + LIF -------------------
#define SMEM_KV ((KW_END + 1024 + 1024)*4)
__global__ __launch_bounds__(512, 1) void k_kv(const float* __restrict__ x,
                                               const float* __restrict__ mx,
                                               const float* __restrict__ Wk,
                                               const float* __restrict__ Wv) {
    extern __shared__ float sm[];
    float* As = sm; float* Ws = sm + ASF; float* Cs = sm;
    float* sCl = sm + KW_END;
    u32* sbal = (u32*)(sm + KW_END + 1024);
    int tid = threadIdx.x, bn0 = blockIdx.x*2;
    int w = tid >> 5, lane = tid & 31;

    {   // A build: raw x*mx (lowpass commutes with feature GEMM)
        int k = tid & 127, q4 = tid >> 7, bnl = q4 >> 1, t0 = (q4 & 1)*32;
        int bn = bn0 + bnl, b = bn >> 6, n = bn & 63;
        const float* xp = x + (size_t)bn*128 + k;
        const float* mp = mx + ((size_t)n*B_ + b)*T_*128 + k;
        float* ad = As + k*RP + bnl*64;
        #pragma unroll 8
        for (int i = 0; i < 32; i++) {
            int t = t0 + i;
            float m = mp[(size_t)t*128];
            m = 0.05f*m + 0.95f*m;
            ad[t] = xp[(size_t)t*PLANE] * m;
        }
    }
    {   // Ws cols 0..127 = Wk, 128..255 = Wv
        const float4* Kg = (const float4*)Wk;
        const float4* Vg = (const float4*)Wv;
        float4* Wm = (float4*)Ws;
        #pragma unroll
        for (int i = tid; i < 8192; i += 512) {
            int row = i >> 6, cq = i & 63;
            Wm[i] = (cq < 32) ? Kg[row*32 + cq] : Vg[row*32 + (cq - 32)];
        }
    }
    for (int i = tid; i < 1024; i += 512) sCl[i] = g_Cl[i];
    __syncthreads();
    u64 acc[4][8];
    #pragma unroll
    for (int p = 0; p < 4; p++)
        #pragma unroll
        for (int j = 0; j < 8; j++) acc[p][j] = 0ull;
    gemm_bc<2>(As, Ws, acc, w, lane);
    __syncthreads();
    store_bc<2>(Cs, acc, w, lane);
    __syncthreads();

    {   // lowpass + LIF; thread = (bnl, col) over 512
        int bnl = tid >> 8, col = tid & 255;
        const float* cc = Cs + col*CP + bnl*64;
        float ca[32], Xk[KK_];
        #pragma unroll
        for (int i = 0; i < 32; i++) ca[i] = cc[i];
        #pragma unroll
        for (int k = 0; k < KK_; k++) {
            float s = 0.f;
            #pragma unroll
            for (int i = 0; i < 32; i++) s += sCl[k*64 + i]*ca[i];
            Xk[k] = s;
        }
        #pragma unroll
        for (int i = 0; i < 32; i++) ca[i] = cc[32 + i];
        #pragma unroll
        for (int k = 0; k < KK_; k++) {
            float s = Xk[k];
            #pragma unroll
            for (int i = 0; i < 32; i++) s += sCl[k*64 + 32 + i]*ca[i];
            Xk[k] = s;
        }
        float v = 0.f;
        for (int t = 0; t < T_; t++) {
            float lp = 0.f;
            #pragma unroll
            for (int k = 0; k < KK_; k++) lp += sCl[k*64 + t]*Xk[k];
            v += (lp - v)*0.5f;
            bool s = (v >= 1.0f); if (s) v = 0.f;
            u32 bal = __ballot_sync(0xffffffffu, s);
            if ((tid & 31) == 0) sbal[t*16 + bnl*8 + (col >> 5)] = bal;
        }
    }
    __syncthreads();
    {   // assemble: it 0,1 = K h0,h1 ; 2,3 = V h0,h1
        int bnl = tid >> 8, rr = tid & 255, t = rr >> 2, it = rr & 3;
        int g = bnl*8 + 2*it;
        u64 bits = (u64)sbal[t*16 + g] | ((u64)sbal[t*16 + g + 1] << 32);
        int bn = bn0 + bnl, b = bn >> 6, n = bn & 63;
        int h = it & 1;
        size_t idx = (((size_t)t*B_ + b)*H_ + h)*N_ + n;
        if (it < 2) g_kbits[idx] = bits; else g_vbits[idx] = bits;
    }
}

// ---------------- K3: attention as broadcast-A mini-GEMM ----------------------
// Per (t,b): cntT[m][hn] = popc(q&k) ; vfs[h*64+m][d] = 0.125*bit (exact).
// o[hn][d] = sum_m cntT[m][hn] * vfs[h*64+m][d].  256 thr = 8 warps:
// warp w = 16 rows (hn) w*16.. (A broadcast), lane = 2 cols lane*2..
#define AT_VP 66
#define SMEM_A ((768 + 8192 + 128*AT_VP)*4)
__global__ __launch_bounds__(256, 3) void k_attn() {
    extern __shared__ float sm[];
    u64* qb = (u64*)sm;           // 128
    u64* kb = qb + 128;
    u64* vb = kb + 128;
    float* cnt_s = sm + 768;      // [64 m][128 hn]
    float* vfs   = sm + 768 + 8192;  // [128 hm][AT_VP]
    int tb = blockIdx.x, t = tb >> 6, b = tb & 63;
    int tid = threadIdx.x;
    size_t base = ((size_t)t*B_ + b)*H_*N_;
    if (tid < 128) {
        qb[tid] = g_qbits[base + tid];
        kb[tid] = g_kbits[base + tid];
        vb[tid] = g_vbits[base + tid];
    }
    __syncthreads();
    {   // vfs build (pre-scaled by 1/8, exact)
        int hm = tid & 127, dh = (tid >> 7)*32;
        u64 vrow = vb[hm];
        float* vd = vfs + hm*AT_VP + dh;
        #pragma unroll 8
        for (int i = 0; i < 32; i++) vd[i] = ((vrow >> (dh + i)) & 1ull) ? 0.125f : 0.f;
    }
    {   // cnt build
        int hn = tid & 127, m0 = (tid >> 7)*32;
        int h = hn >> 6;
        u64 qn = qb[hn];
        #pragma unroll 8
        for (int m = m0; m < m0 + 32; m++)
            cnt_s[m*128 + hn] = (float)__popcll(qn & kb[h*64 + m]);
    }
    __syncthreads();

    int w = tid >> 5, lane = tid & 31;
    int r0 = w*16, h = r0 >> 6;
    const float* Ap = cnt_s + r0;
    const float* Wp = vfs + h*64*AT_VP + lane*2;
    u64 acc[8][2];
    #pragma unroll
    for (int p = 0; p < 8; p++) { acc[p][0] = 0ull; acc[p][1] = 0ull; }
    #pragma unroll 4
    for (int k = 0; k < 64; k++) {
        const float* ar = Ap + k*128;
        ulonglong2 a01 = *(const ulonglong2*)ar;        // broadcast
        ulonglong2 a23 = *(const ulonglong2*)(ar + 4);
        ulonglong2 a45 = *(const ulonglong2*)(ar + 8);
        ulonglong2 a67 = *(const ulonglong2*)(ar + 12);
        float2 wv = *(const float2*)(Wp + k*AT_VP);     // contiguous
        u64 w0 = pk2(wv.x, wv.x), w1 = pk2(wv.y, wv.y);
        ffma2(acc[0][0], a01.x, w0); ffma2(acc[0][1], a01.x, w1);
        ffma2(acc[1][0], a01.y, w0); ffma2(acc[1][1], a01.y, w1);
        ffma2(acc[2][0], a23.x, w0); ffma2(acc[2][1], a23.x, w1);
        ffma2(acc[3][0], a23.y, w0); ffma2(acc[3][1], a23.y, w1);
        ffma2(acc[4][0], a45.x, w0); ffma2(acc[4][1], a45.x, w1);
        ffma2(acc[5][0], a45.y, w0); ffma2(acc[5][1], a45.y, w1);
        ffma2(acc[6][0], a67.x, w0); ffma2(acc[6][1], a67.x, w1);
        ffma2(acc[7][0], a67.y, w0); ffma2(acc[7][1], a67.y, w1);
    }
    size_t obase = ((size_t)t*B_ + b)*N_*128;
    #pragma unroll
    for (int p = 0; p < 8; p++) {
        int r = r0 + 2*p;
        int n0 = r & 63;
        float2 f0 = up2(acc[p][0]);   // rows r,r+1 @ col c0
        float2 f1 = up2(acc[p][1]);   // rows r,r+1 @ col c0+1
        *(float2*)(g_o + obase + (size_t)n0*128 + h*64 + lane*2)       = make_float2(f0.x, f1.x);
        *(float2*)(g_o + obase + (size_t)(n0 + 1)*128 + h*64 + lane*2) = make_float2(f0.y, f1.y);
    }
}

// ---------------- K6: xg @ W1 (128->256) fused + LIF -> m1 bitmaps -------------
#define SMEM_W1 ((KW_END + 512 + 1024)*4)
__global__ __launch_bounds__(512, 1) void k_w1(const float* __restrict__ x,
                                               const float* __restrict__ W1) {
    extern __shared__ float sm[];
    float* As = sm; float* Ws = sm + ASF; float* Cs = sm;
    u64* sab = (u64*)(sm + KW_END);
    u32* sbal = (u32*)(sm + KW_END + 512);
    int tid = threadIdx.x, bn0 = blockIdx.x*2;
    int w = tid >> 5, lane = tid & 31;

    if (tid < 256) {
        int bnl = tid >> 7, rr = tid & 127, t = rr >> 1, ww = rr & 1;
        int bn = bn0 + bnl, b = bn >> 6, n = bn & 63;
        sab[bnl*128 + t*2 + ww] = g_abits[(((size_t)t*B_ + b)*N_ + n)*H_ + ww];
    }
    {
        const float4* Wg = (const float4*)W1;
        float4* Wm = (float4*)Ws;
        #pragma unroll
        for (int i = tid; i < 8192; i += 512) Wm[i] = Wg[i];
    }
    __syncthreads();
    {   // A build: xg = x * (1 - attn_spk)
        int k = tid & 127, q4 = tid >> 7, bnl = q4 >> 1, t0 = (q4 & 1)*32;
        const float* xp = x + (size_t)(bn0 + bnl)*128 + k;
        float* ad = As + k*RP + bnl*64;
        #pragma unroll 8
        for (int i = 0; i < 32; i++) {
            int t = t0 + i;
            u64 ab = sab[bnl*128 + t*2 + (k >> 6)];
            float gt = ((ab >> (k & 63)) & 1ull) ? 0.f : 1.f;
            ad[t] = xp[(size_t)t*PLANE] * gt;
        }
    }
    __syncthreads();
    u64 acc[4][8];
    #pragma unroll
    for (int p = 0; p < 4; p++)
        #pragma unroll
        for (int j = 0; j < 8; j++) acc[p][j] = 0ull;
    gemm_bc<2>(As, Ws, acc, w, lane);
    __syncthreads();
    store_bc<2>(Cs, acc, w, lane);
    __syncthreads();

    {   // LIF over 512 (bnl,col)
        int bnl = tid >> 8, col = tid & 255;
        const float* cc = Cs + col*CP + bnl*64;
        float v = 0.f;
        for (int t = 0; t < T_; t++) {
            float c = cc[t];
            v += (c - v)*0.5f;
            bool s = (v >= 1.0f); if (s) v = 0.f;
            u32 bal = __ballot_sync(0xffffffffu, s);
            if ((tid & 31) == 0) sbal[t*16 + bnl*8 + (col >> 5)] = bal;
        }
    }
    __syncthreads();
    {
        int bnl = tid >> 8, rr = tid & 255, t = rr >> 2, word = rr & 3;
        int g = bnl*8 + 2*word;
        u64 bits = (u64)sbal[t*16 + g] | ((u64)sbal[t*16 + g + 1] << 32);
        int bn = bn0 + bnl, b = bn >> 6, n = bn & 63;
        g_m1bits[(((size_t)t*B_ + b)*N_ + n)*4 + word] = bits;
    }
}

// ---------------- K7: sparse m1 @ W2 + LIF + final gated output ---------------
#define SMEM_W2 (256*128*4 + 1024*8 + 512*8)
__global__ __launch_bounds__(512, 1) void k_w2(const float* __restrict__ x,
                                               const float* __restrict__ W2,
                                               float* __restrict__ out) {
    extern __shared__ float sm[];
    float* W2s = sm;
    u64* sm1 = (u64*)(sm + 256*128);
    u64* sab = sm1 + 1024;
    int tid = threadIdx.x, bn0 = blockIdx.x*4;
    int grp = tid >> 7, d = tid & 127;

    {
        const float4* Wg = (const float4*)W2;
        float4* Wm = (float4*)W2s;
        #pragma unroll
        for (int i = tid; i < 8192; i += 512) Wm[i] = Wg[i];
    }
    #pragma unroll
    for (int i = tid; i < 1024; i += 512) {
        int g = i >> 8, rr = i & 255, t = rr >> 2, ww = rr & 3;
        int bn = bn0 + g, b = bn >> 6, n = bn & 63;
        sm1[i] = g_m1bits[(((size_t)t*B_ + b)*N_ + n)*4 + ww];
    }
    {
        int g = tid >> 7, rr = tid & 127, t = rr >> 1, ww = rr & 1;
        int bn = bn0 + g, b = bn >> 6, n = bn & 63;
        sab[tid] = g_abits[(((size_t)t*B_ + b)*N_ + n)*H_ + ww];
    }
    __syncthreads();

    int bn = bn0 + grp;
    const u64* mrow = sm1 + grp*256;
    const u64* arow = sab + grp*128;
    float v = 0.f;
    for (int t = 0; t < T_; t++) {
        float a0 = 0.f, a1 = 0.f;
        #pragma unroll
        for (int ww = 0; ww < 4; ww += 2) {
            u64 bb = mrow[t*4 + ww];
            while (bb) { int k2 = __ffsll((long long)bb) - 1; bb &= bb - 1ull; a0 += W2s[(ww*64 + k2)*128 + d]; }
            u64 bc = mrow[t*4 + ww + 1];
            while (bc) { int k2 = __ffsll((long long)bc) - 1; bc &= bc - 1ull; a1 += W2s[((ww + 1)*64 + k2)*128 + d]; }
        }
        float a = a0 + a1;
        v += (a - v)*0.5f;
        bool s = (v >= 1.0f); if (s) v = 0.f;
        u32 ag = (u32)((arow[t*2 + (d >> 6)] >> (d & 63)) & 1ull);
        size_t off = (size_t)t*PLANE + (size_t)bn*128 + d;
        out[off] = (s || ag) ? 0.f : x[off];
    }
}

// ---------------- launch ------------------------------------------------------
extern "C" void kernel_launch(void* const* d_in, const int* in_sizes, int n_in,
                              void* d_out, int out_size) {
    const float* x  = (const float*)d_in[0];
    const float* mx = (const float*)d_in[1];
    const float* Wq = (const float*)d_in[2];
    const float* Wk = (const float*)d_in[3];
    const float* Wv = (const float*)d_in[4];
    const float* Wo = (const float*)d_in[5];
    const float* W1 = (const float*)d_in[6];
    const float* W2 = (const float*)d_in[7];
    float* out = (float*)d_out;

    static float* s_o = nullptr;
    if (!s_o) { void* p = nullptr; cudaGetSymbolAddress(&p, g_o); s_o = (float*)p; }
    static bool s_attr = false;
    if (!s_attr) {
        cudaFuncSetAttribute(k_g128, cudaFuncAttributeMaxDynamicSharedMemorySize, SMEM_G);
        cudaFuncSetAttribute(k_kv,   cudaFuncAttributeMaxDynamicSharedMemorySize, SMEM_KV);
        cudaFuncSetAttribute(k_attn, cudaFuncAttributeMaxDynamicSharedMemorySize, SMEM_A);
        cudaFuncSetAttribute(k_w1,   cudaFuncAttributeMaxDynamicSharedMemorySize, SMEM_W1);
        cudaFuncSetAttribute(k_w2,   cudaFuncAttributeMaxDynamicSharedMemorySize, SMEM_W2);
        s_attr = true;
    }

    // slot 4 = k_attn (the one ncu captures)
    k_dct<<<1, dim3(T_, KK_)>>>();                        // 1
    k_g128<<<2048, 512, SMEM_G>>>(x, Wq, 0);              // 2
    k_kv<<<2048, 512, SMEM_KV>>>(x, mx, Wk, Wv);          // 3
    k_attn<<<T_*B_, 256, SMEM_A>>>();                     // 4 <- profiled
    k_g128<<<2048, 512, SMEM_G>>>(s_o, Wo, 1);            // 5
    k_w1<<<2048, 512, SMEM_W1>>>(x, W1);                  // 6
    k_w2<<<1024, 512, SMEM_W2>>>(x, W2, out);             // 7
}